// round 14
// baseline (speedup 1.0000x reference)
#include <cuda_runtime.h>
#include <cstdint>

// ---------------------------------------------------------------------------
// Router: r[b,e] = || W[e] @ x[b] ||_2
//   x: [8192,4096] f32, W: [16,64,4096] f32, out: [8192,16] f32
// GEMM C = X @ W^T via mma.sync.m16n8k16.bf16 (base sm_103 target).
// R14 vs R13 (248.3us = 29 prep + 217 GEMM): R13's profile shows the tensor
// pipe only 51.7% active (~2 SM-cyc pipe occupancy per HMMA -> ~120us pipe
// floor); the gap is dependency holes at 2 warps/SMSP. -> 512 threads
// (16 warps, 4/SMSP), warp tile 32x64 (still one expert per warp).
// Registers engineered under the 128 cap: acc 64 + A frags 16 + B frags in
// two groups of 4 (16) ~ 96 + addressing. Everything else is R13 verbatim
// (3-stage cp.async, RSB=192, k-slot-remap LDS.128, fused bf16 prep).
// ---------------------------------------------------------------------------

#define BDIM   8192
#define DDIM   4096
#define EDIM   16
#define NTOT   1024
#define BM     128
#define BN     256
#define BK     64                      /* bf16 cols per stage = 128B/row    */
#define STAGES 3
#define KT     (DDIM / BK)             /* 64 mainloop iterations            */
#define RSB    192                     /* smem row stride bytes (=64 mod 128:
                                          conflict-free 16B phases)          */
#define A_BYTES (BM * RSB)             /* 24576 */
#define B_BYTES (BN * RSB)             /* 49152 */
#define STG_BYTES (A_BYTES + B_BYTES)  /* 73728 */
#define SMEM_BYTES (STAGES * STG_BYTES)/* 221184 */

#define NX16 ((size_t)BDIM * DDIM / 16)
#define NW16 ((size_t)NTOT * DDIM / 16)

// bf16 scratch copies of the inputs (module-scope __device__ = legal scratch)
__device__ uint4 g_xb[(size_t)BDIM * DDIM / 8];   // 67 MB
__device__ uint4 g_wb[(size_t)NTOT * DDIM / 8];   //  8.4 MB

__device__ __forceinline__ void mma_bf16(float c[4],
                                         uint32_t a0, uint32_t a1,
                                         uint32_t a2, uint32_t a3,
                                         uint32_t b0, uint32_t b1) {
    asm volatile(
        "mma.sync.aligned.m16n8k16.row.col.f32.bf16.bf16.f32 "
        "{%0,%1,%2,%3}, {%4,%5,%6,%7}, {%8,%9}, {%0,%1,%2,%3};"
        : "+f"(c[0]), "+f"(c[1]), "+f"(c[2]), "+f"(c[3])
        : "r"(a0), "r"(a1), "r"(a2), "r"(a3), "r"(b0), "r"(b1));
}

__device__ __forceinline__ void cp16(uint32_t dst, const void* src) {
    asm volatile("cp.async.cg.shared.global [%0], [%1], 16;"
                 :: "r"(dst), "l"(src) : "memory");
}

__device__ __forceinline__ uint32_t pack_bf16x2(float lo, float hi) {
    uint32_t r;
    asm("cvt.rn.bf16x2.f32 %0, %1, %2;" : "=r"(r) : "f"(hi), "f"(lo));
    return r;
}

// ---------------------------------------------------------------------------
// Fused prep: f32 -> bf16 (RN, unbiased) for x and w in one launch.
// 16 floats per thread: 4x LDG.128 + 2x STG.128.
// ---------------------------------------------------------------------------
__global__ void prep_xw(const float4* __restrict__ x,
                        const float4* __restrict__ w) {
    size_t i = (size_t)blockIdx.x * blockDim.x + threadIdx.x;
    const float4* src;
    uint4* dst;
    if (i < NX16) {
        src = x + 4 * i;              dst = g_xb + 2 * i;
    } else {
        size_t j = i - NX16;
        if (j >= NW16) return;
        src = w + 4 * j;              dst = g_wb + 2 * j;
    }
    float4 v0 = src[0], v1 = src[1], v2 = src[2], v3 = src[3];
    uint4 o0, o1;
    o0.x = pack_bf16x2(v0.x, v0.y);
    o0.y = pack_bf16x2(v0.z, v0.w);
    o0.z = pack_bf16x2(v1.x, v1.y);
    o0.w = pack_bf16x2(v1.z, v1.w);
    o1.x = pack_bf16x2(v2.x, v2.y);
    o1.y = pack_bf16x2(v2.z, v2.w);
    o1.z = pack_bf16x2(v3.x, v3.y);
    o1.w = pack_bf16x2(v3.z, v3.w);
    dst[0] = o0;
    dst[1] = o1;
}

// ---------------------------------------------------------------------------
// grid = (NTOT/BN = 4, BDIM/BM = 64), n fastest (A reused via L2).
// 16 warps: 4(m) x 4(n); warp tile 32x64 = one expert per warp.
// k-slot remap per 32-col chunk: one LDS.128 per row feeds both m16n8k16
// instances (fragment halves .x/.y vs .z/.w).
// ---------------------------------------------------------------------------
__global__ __launch_bounds__(512, 1)
void router_kernel(float* __restrict__ out) {
    extern __shared__ char smem[];

    const int tid  = threadIdx.x;
    const int lane = tid & 31;
    const int wid  = tid >> 5;              // 0..15
    const int wm   = wid & 3;               // 0..3 (32 m-rows each)
    const int wn   = wid >> 2;              // 0..3 (expert)

    const int m_base = blockIdx.y * BM;
    const int n_base = blockIdx.x * BN;

    // ---- cp.async producer: thread -> (row = tid/8, 16B chunk = tid%8) ----
    const int lrow = tid >> 3;               // 0..63
    const int lch  = tid & 7;                // 0..7
    const char* gA = (const char*)g_xb
                   + ((size_t)(m_base + lrow) * DDIM + lch * 8) * 2;
    const char* gB = (const char*)g_wb
                   + ((size_t)(n_base + lrow) * DDIM + lch * 8) * 2;
    const uint32_t sbase = (uint32_t)__cvta_generic_to_shared(smem);
    const uint32_t sA0 = sbase + (uint32_t)(lrow * RSB + lch * 16);
    const uint32_t sB0 = sA0 + A_BYTES;

    auto load_stage = [&](int s, int kb /*bf16 col offset*/) {
        const uint32_t so = (uint32_t)(s * STG_BYTES);
        const char* ga = gA + (size_t)kb * 2;
#pragma unroll
        for (int p = 0; p < BM / 64; ++p)    // 2 passes of 64 rows
            cp16(sA0 + so + (uint32_t)(p * 64 * RSB),
                 ga + (size_t)(p * 64) * DDIM * 2);
        const char* gb = gB + (size_t)kb * 2;
#pragma unroll
        for (int p = 0; p < BN / 64; ++p)    // 4 passes of 64 rows
            cp16(sB0 + so + (uint32_t)(p * 64 * RSB),
                 gb + (size_t)(p * 64) * DDIM * 2);
    };

#pragma unroll
    for (int s = 0; s < STAGES - 1; ++s) {
        load_stage(s, s * BK);
        asm volatile("cp.async.commit_group;" ::: "memory");
    }

    float acc[2][8][4];
#pragma unroll
    for (int mt = 0; mt < 2; ++mt)
#pragma unroll
        for (int nt = 0; nt < 8; ++nt)
#pragma unroll
            for (int i = 0; i < 4; ++i) acc[mt][nt][i] = 0.f;

    const int g = lane >> 2;                 // group (row) id
    const int q = lane & 3;                  // quad id
    const char* Aw = smem + (wm * 32 + g) * RSB + q * 16;
    const char* Bw = smem + A_BYTES + (wn * 64 + g) * RSB + q * 16;

#pragma unroll 1
    for (int kt = 0; kt < KT; ++kt) {
        asm volatile("cp.async.wait_group %0;" :: "n"(STAGES - 2) : "memory");
        __syncthreads();

        const int pf = kt + STAGES - 1;
        if (pf < KT) load_stage(pf % STAGES, pf * BK);
        asm volatile("cp.async.commit_group;" ::: "memory");

        const int cur = kt % STAGES;
        const char* Ac = Aw + cur * STG_BYTES;
        const char* Bc = Bw + cur * STG_BYTES;

#pragma unroll
        for (int c2 = 0; c2 < 2; ++c2) {     // two 32-col chunks per stage
            const int co = c2 * 64;
            uint4 al[2], ah[2];              // A rows g, g+8 per mt
#pragma unroll
            for (int mt = 0; mt < 2; ++mt) {
                const char* p = Ac + mt * 16 * RSB + co;
                al[mt] = *reinterpret_cast<const uint4*>(p);
                ah[mt] = *reinterpret_cast<const uint4*>(p + 8 * RSB);
            }
            // B in two groups of 4 to bound live registers (< 128-reg cap)
#pragma unroll
            for (int ng = 0; ng < 2; ++ng) {
                uint4 bv[4];
#pragma unroll
                for (int j = 0; j < 4; ++j)
                    bv[j] = *reinterpret_cast<const uint4*>(
                                Bc + ((ng * 4 + j) * 8) * RSB + co);
                // instance 0: fragment halves .x/.y
#pragma unroll
                for (int mt = 0; mt < 2; ++mt)
#pragma unroll
                    for (int j = 0; j < 4; ++j)
                        mma_bf16(acc[mt][ng * 4 + j],
                                 al[mt].x, ah[mt].x, al[mt].y, ah[mt].y,
                                 bv[j].x, bv[j].y);
                // instance 1: fragment halves .z/.w
#pragma unroll
                for (int mt = 0; mt < 2; ++mt)
#pragma unroll
                    for (int j = 0; j < 4; ++j)
                        mma_bf16(acc[mt][ng * 4 + j],
                                 al[mt].z, ah[mt].z, al[mt].w, ah[mt].w,
                                 bv[j].z, bv[j].w);
            }
        }
    }

    // ---- epilogue: ||.||_2 over this warp's 64 n-cols (one expert) --------
    const int e = blockIdx.x * (BN / 64) + wn;
#pragma unroll
    for (int mt = 0; mt < 2; ++mt) {
        float s0 = 0.f, s1 = 0.f;
#pragma unroll
        for (int nt = 0; nt < 8; ++nt) {
            s0 = fmaf(acc[mt][nt][0], acc[mt][nt][0], s0);
            s0 = fmaf(acc[mt][nt][1], acc[mt][nt][1], s0);
            s1 = fmaf(acc[mt][nt][2], acc[mt][nt][2], s1);
            s1 = fmaf(acc[mt][nt][3], acc[mt][nt][3], s1);
        }
        s0 += __shfl_xor_sync(0xffffffffu, s0, 1);
        s0 += __shfl_xor_sync(0xffffffffu, s0, 2);
        s1 += __shfl_xor_sync(0xffffffffu, s1, 1);
        s1 += __shfl_xor_sync(0xffffffffu, s1, 2);
        if ((lane & 3) == 0) {
            const int row = m_base + wm * 32 + mt * 16 + g;
            out[(size_t)row * EDIM + e]       = sqrtf(s0);
            out[(size_t)(row + 8) * EDIM + e] = sqrtf(s1);
        }
    }
}

// ---------------------------------------------------------------------------
extern "C" void kernel_launch(void* const* d_in, const int* in_sizes, int n_in,
                              void* d_out, int out_size) {
    (void)in_sizes; (void)n_in; (void)out_size;
    const float* x = (const float*)d_in[0];   // [8192, 4096]
    const float* w = (const float*)d_in[1];   // [16, 64, 4096]
    float* out = (float*)d_out;               // [8192, 16]

    const size_t total = NX16 + NW16;
    prep_xw<<<(unsigned)((total + 255) / 256), 256>>>(
        (const float4*)x, (const float4*)w);

    cudaFuncSetAttribute(router_kernel,
                         cudaFuncAttributeMaxDynamicSharedMemorySize, SMEM_BYTES);
    router_kernel<<<dim3(NTOT / BN, BDIM / BM), 512, SMEM_BYTES>>>(out);
}

// round 15
// speedup vs baseline: 1.2139x; 1.2139x over previous
#include <cuda_runtime.h>
#include <cstdint>

// ---------------------------------------------------------------------------
// Router: r[b,e] = || W[e] @ x[b] ||_2
//   x: [8192,4096] f32, W: [16,64,4096] f32, out: [8192,16] f32
// GEMM C = X @ W^T via mma.sync.m16n8k16.bf16 (base sm_103 target).
// R15 vs R13 (248.3us = 29 prep + 217 GEMM): R14 falsified the occupancy
// theory (4 w/SMSP regressed, regs clean) -> per-SM HMMA service rate is
// fixed; the ~90us above the ~127us pipe floor is per-iteration overhead
// (64 lockstep barriers + 64 cold LDS->MMA restarts). -> BK 64->128:
// 32 iterations, 2 stages, same compute shape per 32-col chunk as R13.
// Padding doesn't fit at BK=128, so XOR swizzle (chunk ^= (row&1)<<2,
// row stride 256): enumerated conflict-free (even rows banks {4c..4c+3},
// odd rows the complement). SMEM 2x96KB = 196.6KB. Prep/epilogue unchanged.
// ---------------------------------------------------------------------------

#define BDIM   8192
#define DDIM   4096
#define EDIM   16
#define NTOT   1024
#define BM     128
#define BN     256
#define BK     128                     /* bf16 cols per stage = 256B/row    */
#define STAGES 2
#define KT     (DDIM / BK)             /* 32 mainloop iterations            */
#define RS     256                     /* smem row stride bytes (swizzled)  */
#define A_BYTES (BM * RS)              /* 32768 */
#define B_BYTES (BN * RS)              /* 65536 */
#define STG_BYTES (A_BYTES + B_BYTES)  /* 98304 */
#define SMEM_BYTES (STAGES * STG_BYTES)/* 196608 */

#define NX16 ((size_t)BDIM * DDIM / 16)
#define NW16 ((size_t)NTOT * DDIM / 16)

// bf16 scratch copies of the inputs (module-scope __device__ = legal scratch)
__device__ uint4 g_xb[(size_t)BDIM * DDIM / 8];   // 67 MB
__device__ uint4 g_wb[(size_t)NTOT * DDIM / 8];   //  8.4 MB

__device__ __forceinline__ void mma_bf16(float c[4],
                                         uint32_t a0, uint32_t a1,
                                         uint32_t a2, uint32_t a3,
                                         uint32_t b0, uint32_t b1) {
    asm volatile(
        "mma.sync.aligned.m16n8k16.row.col.f32.bf16.bf16.f32 "
        "{%0,%1,%2,%3}, {%4,%5,%6,%7}, {%8,%9}, {%0,%1,%2,%3};"
        : "+f"(c[0]), "+f"(c[1]), "+f"(c[2]), "+f"(c[3])
        : "r"(a0), "r"(a1), "r"(a2), "r"(a3), "r"(b0), "r"(b1));
}

__device__ __forceinline__ void cp16(uint32_t dst, const void* src) {
    asm volatile("cp.async.cg.shared.global [%0], [%1], 16;"
                 :: "r"(dst), "l"(src) : "memory");
}

__device__ __forceinline__ uint32_t pack_bf16x2(float lo, float hi) {
    uint32_t r;
    asm("cvt.rn.bf16x2.f32 %0, %1, %2;" : "=r"(r) : "f"(hi), "f"(lo));
    return r;
}

// ---------------------------------------------------------------------------
// Fused prep: f32 -> bf16 (RN, unbiased) for x and w in one launch.
// ---------------------------------------------------------------------------
__global__ void prep_xw(const float4* __restrict__ x,
                        const float4* __restrict__ w) {
    size_t i = (size_t)blockIdx.x * blockDim.x + threadIdx.x;
    const float4* src;
    uint4* dst;
    if (i < NX16) {
        src = x + 4 * i;              dst = g_xb + 2 * i;
    } else {
        size_t j = i - NX16;
        if (j >= NW16) return;
        src = w + 4 * j;              dst = g_wb + 2 * j;
    }
    float4 v0 = src[0], v1 = src[1], v2 = src[2], v3 = src[3];
    uint4 o0, o1;
    o0.x = pack_bf16x2(v0.x, v0.y);
    o0.y = pack_bf16x2(v0.z, v0.w);
    o0.z = pack_bf16x2(v1.x, v1.y);
    o0.w = pack_bf16x2(v1.z, v1.w);
    o1.x = pack_bf16x2(v2.x, v2.y);
    o1.y = pack_bf16x2(v2.z, v2.w);
    o1.z = pack_bf16x2(v3.x, v3.y);
    o1.w = pack_bf16x2(v3.z, v3.w);
    dst[0] = o0;
    dst[1] = o1;
}

// ---------------------------------------------------------------------------
// grid = (NTOT/BN = 4, BDIM/BM = 64), n fastest (A reused via L2).
// 8 warps: 2(m) x 4(n); warp tile 64x64 = one expert per warp (R13 shape).
// Swizzle: 16B chunk index c at row r lives at r*256 + (c ^ ((r&1)<<2))*16.
// k-slot remap per 32-col chunk: one LDS.128 per row feeds both m16n8k16
// instances (fragment halves .x/.y vs .z/.w).
// ---------------------------------------------------------------------------
__global__ __launch_bounds__(256, 1)
void router_kernel(float* __restrict__ out) {
    extern __shared__ char smem[];

    const int tid  = threadIdx.x;
    const int lane = tid & 31;
    const int wid  = tid >> 5;
    const int wm   = wid & 1;
    const int wn   = wid >> 1;

    const int m_base = blockIdx.y * BM;
    const int n_base = blockIdx.x * BN;

    const uint32_t sbase = (uint32_t)__cvta_generic_to_shared(smem);

    // ---- cp.async producer: thread -> (row = tid/16, 16B chunk = tid%16) --
    const int lrow = tid >> 4;               // 0..15
    const int lch  = tid & 15;               // 0..15 (16 chunks per 256B row)
    const int swch = lch ^ ((lrow & 1) << 2);              // swizzled chunk
    const char* gA = (const char*)g_xb
                   + ((size_t)(m_base + lrow) * DDIM + lch * 8) * 2;
    const char* gB = (const char*)g_wb
                   + ((size_t)(n_base + lrow) * DDIM + lch * 8) * 2;
    const uint32_t sA0 = sbase + (uint32_t)(lrow * RS + swch * 16);
    const uint32_t sB0 = sA0 + A_BYTES;

    auto load_stage = [&](int s, int kb /*bf16 col offset*/) {
        const uint32_t so = (uint32_t)(s * STG_BYTES);
        const char* ga = gA + (size_t)kb * 2;
#pragma unroll
        for (int p = 0; p < BM / 16; ++p)    // 8 passes of 16 rows (A)
            cp16(sA0 + so + (uint32_t)(p * 16 * RS),
                 ga + (size_t)(p * 16) * DDIM * 2);
        const char* gb = gB + (size_t)kb * 2;
#pragma unroll
        for (int p = 0; p < BN / 16; ++p)    // 16 passes of 16 rows (B)
            cp16(sB0 + so + (uint32_t)(p * 16 * RS),
                 gb + (size_t)(p * 16) * DDIM * 2);
    };

    load_stage(0, 0);
    asm volatile("cp.async.commit_group;" ::: "memory");

    float acc[4][8][4];
#pragma unroll
    for (int mt = 0; mt < 4; ++mt)
#pragma unroll
        for (int nt = 0; nt < 8; ++nt)
#pragma unroll
            for (int i = 0; i < 4; ++i) acc[mt][nt][i] = 0.f;

    const int g = lane >> 2;                 // group (row) id
    const int q = lane & 3;                  // quad id
    const int xm = (g & 1) << 2;             // row-parity swizzle mask
    const char* Aw = smem + (wm * 64 + g) * RS;
    const char* Bw = smem + A_BYTES + (wn * 64 + g) * RS;

#pragma unroll 1
    for (int kt = 0; kt < KT; ++kt) {
        asm volatile("cp.async.wait_group 0;" ::: "memory");
        __syncthreads();

        if (kt + 1 < KT) load_stage((kt + 1) & 1, (kt + 1) * BK);
        asm volatile("cp.async.commit_group;" ::: "memory");

        const int cur = kt & 1;
        const char* Ac = Aw + cur * STG_BYTES;
        const char* Bc = Bw + cur * STG_BYTES;

#pragma unroll
        for (int c2 = 0; c2 < 4; ++c2) {     // four 32-col chunks per stage
            const int co = ((c2 * 4 + q) ^ xm) * 16;      // swizzled offset
            uint4 al[4], ah[4];              // A rows g, g+8 per mt
#pragma unroll
            for (int mt = 0; mt < 4; ++mt) {
                const char* p = Ac + mt * 16 * RS + co;
                al[mt] = *reinterpret_cast<const uint4*>(p);
                ah[mt] = *reinterpret_cast<const uint4*>(p + 8 * RS);
            }
            uint4 bv[8];
#pragma unroll
            for (int nt = 0; nt < 8; ++nt)
                bv[nt] = *reinterpret_cast<const uint4*>(Bc + nt * 8 * RS + co);

            // instance 0: fragment halves .x/.y — 32 independent acc chains
#pragma unroll
            for (int mt = 0; mt < 4; ++mt)
#pragma unroll
                for (int nt = 0; nt < 8; ++nt)
                    mma_bf16(acc[mt][nt],
                             al[mt].x, ah[mt].x, al[mt].y, ah[mt].y,
                             bv[nt].x, bv[nt].y);
            // instance 1: fragment halves .z/.w
#pragma unroll
            for (int mt = 0; mt < 4; ++mt)
#pragma unroll
                for (int nt = 0; nt < 8; ++nt)
                    mma_bf16(acc[mt][nt],
                             al[mt].z, ah[mt].z, al[mt].w, ah[mt].w,
                             bv[nt].z, bv[nt].w);
        }
    }

    // ---- epilogue: ||.||_2 over this warp's 64 n-cols (one expert) --------
    const int e = blockIdx.x * (BN / 64) + wn;
#pragma unroll
    for (int mt = 0; mt < 4; ++mt) {
        float s0 = 0.f, s1 = 0.f;
#pragma unroll
        for (int nt = 0; nt < 8; ++nt) {
            s0 = fmaf(acc[mt][nt][0], acc[mt][nt][0], s0);
            s0 = fmaf(acc[mt][nt][1], acc[mt][nt][1], s0);
            s1 = fmaf(acc[mt][nt][2], acc[mt][nt][2], s1);
            s1 = fmaf(acc[mt][nt][3], acc[mt][nt][3], s1);
        }
        s0 += __shfl_xor_sync(0xffffffffu, s0, 1);
        s0 += __shfl_xor_sync(0xffffffffu, s0, 2);
        s1 += __shfl_xor_sync(0xffffffffu, s1, 1);
        s1 += __shfl_xor_sync(0xffffffffu, s1, 2);
        if ((lane & 3) == 0) {
            const int row = m_base + wm * 64 + mt * 16 + g;
            out[(size_t)row * EDIM + e]       = sqrtf(s0);
            out[(size_t)(row + 8) * EDIM + e] = sqrtf(s1);
        }
    }
}

// ---------------------------------------------------------------------------
extern "C" void kernel_launch(void* const* d_in, const int* in_sizes, int n_in,
                              void* d_out, int out_size) {
    (void)in_sizes; (void)n_in; (void)out_size;
    const float* x = (const float*)d_in[0];   // [8192, 4096]
    const float* w = (const float*)d_in[1];   // [16, 64, 4096]
    float* out = (float*)d_out;               // [8192, 16]

    const size_t total = NX16 + NW16;
    prep_xw<<<(unsigned)((total + 255) / 256), 256>>>(
        (const float4*)x, (const float4*)w);

    cudaFuncSetAttribute(router_kernel,
                         cudaFuncAttributeMaxDynamicSharedMemorySize, SMEM_BYTES);
    router_kernel<<<dim3(NTOT / BN, BDIM / BM), 256, SMEM_BYTES>>>(out);
}